// round 10
// baseline (speedup 1.0000x reference)
#include <cuda_runtime.h>

// NoQmix: q_tot[b] = sum_j agent_qs[b, j]
//
// Exact identity (verified R4/R6/R7/R8, rel_err 1.7e-7): softmax(e, axis=1)
// sums to 1 per (b,j) column unconditionally, so q_tot[b] = sum_j qs[b,j].
// Only agent_qs (input 1, [4096, 64] fp32) matters: 1.05 MB read + 16 KB write.
//
// Measured floor model: kernel time is 4.4-4.6us INVARIANT across
// 2048/1024/512 warps, MLP 1/2/4, 256/128/64 blocks (R4/R7/R8) ->
// launch/drain overhead + one DRAM round-trip + ramp; DRAM sits at ~3%.
// Harness-level spread {5.98, 5.18, 5.95} on identical kernel times is
// run-to-run noise. This round re-benches the best measured variant (R7:
// 128 blocks x 256 threads, 4 rows/warp, 2 coalesced LDG.128 per lane)
// as the terminal configuration.

static constexpr int B_ROWS = 4096;
static constexpr int N_AGENTS = 64;   // 16 float4 per row

__global__ void noqmix_rowsum_kernel(const float* __restrict__ qs,
                                     float* __restrict__ out) {
    const int gwarp = (blockIdx.x * blockDim.x + threadIdx.x) >> 5;
    const int lane  = threadIdx.x & 31;
    const int sub   = lane >> 4;      // which row of the pair
    const int slane = lane & 15;      // lane within 16-lane row group

    // Warp covers rows [gwarp*4, gwarp*4+4): two coalesced row pairs.
    const int row0 = gwarp * 4 + sub;
    const int row1 = row0 + 2;

    const float4* base = reinterpret_cast<const float4*>(qs);
    float4 va = base[(size_t)row0 * (N_AGENTS / 4) + slane];
    float4 vb = base[(size_t)row1 * (N_AGENTS / 4) + slane];

    float sa = (va.x + va.y) + (va.z + va.w);
    float sb = (vb.x + vb.y) + (vb.z + vb.w);

    // Two independent butterfly chains (xor offsets stay inside 16-lane group).
#pragma unroll
    for (int off = 8; off > 0; off >>= 1) {
        sa += __shfl_xor_sync(0xffffffffu, sa, off);
        sb += __shfl_xor_sync(0xffffffffu, sb, off);
    }

    if (slane == 0) {
        out[row0] = sa;
        out[row1] = sb;
    }
}

extern "C" void kernel_launch(void* const* d_in, const int* in_sizes, int n_in,
                              void* d_out, int out_size) {
    // Input order: features(0), agent_qs(1), adj(2), states(3), W(4), a(5).
    const float* agent_qs = (const float*)d_in[1];
    float* out = (float*)d_out;

    // 4096 rows, 4 rows/warp, 8 warps/block -> 32 rows/block -> 128 blocks.
    const int threads = 256;
    const int rows_per_block = (threads / 32) * 4;          // 32
    const int blocks = B_ROWS / rows_per_block;              // 128 (exact)
    noqmix_rowsum_kernel<<<blocks, threads>>>(agent_qs, out);
}